// round 10
// baseline (speedup 1.0000x reference)
#include <cuda_runtime.h>
#include <cuda_bf16.h>
#include <math.h>

#define N_OP 20000
#define N_M  500
#define NE   200000
#define DD   256
#define HH   8

#define LD_OP 1792   // [q | ka0 | ka1 | ka2 | va0 | va1 | va2]
#define LD_M  768    // [q | ka3 | va3]
#define OPB  2500
#define SCALE 0.17677669529663687f
#define NZB  5000    // initzero blocks
#define WSB  (LD_OP + LD_M)

// ---------------- scratch ----------------
__device__ float g_x0[N_OP * DD];
__device__ __nv_bfloat16 g_proj_op[(size_t)N_OP * LD_OP];
__device__ __nv_bfloat16 g_proj_m[N_M * LD_M];
__device__ float g_wop[LD_OP * DD];
__device__ float g_bop[LD_OP];
__device__ float g_wm[LD_M * DD];
__device__ float g_bm[LD_M];
__device__ float g_out_op[N_OP * DD];
__device__ float g_out_m[N_M * DD];
__device__ float g_tstat[300];
__device__ float g_tacc[N_OP * 20];
#define NCTR (3 * N_OP + N_M)
__device__ int g_cnt[NCTR];
__device__ int g_off[NCTR];
__device__ int g_cur[NCTR];
__device__ int g_elist[4 * NE];

struct GemmCfg {
    const float* A; const float* W; const float* bias; void* C;
    int M, lda, ldc, gx, gy;
    const float* skipX; int skipIdx; int outBF; int amode;
};

__device__ __forceinline__ void red_add_v4(float* p, float4 v) {
    asm volatile("red.global.add.v4.f32 [%0], {%1,%2,%3,%4};"
                 :: "l"(p), "f"(v.x), "f"(v.y), "f"(v.z), "f"(v.w) : "memory");
}

__device__ __forceinline__ unsigned f2tf32(float f) {
    unsigned u; asm("cvt.rna.tf32.f32 %0, %1;" : "=r"(u) : "f"(f)); return u;
}

__device__ __forceinline__ void mma_tf32(float* c, unsigned a0, unsigned a1,
                                         unsigned a2, unsigned a3,
                                         unsigned b0, unsigned b1) {
    asm volatile("mma.sync.aligned.m16n8k8.row.col.f32.tf32.tf32.f32 "
                 "{%0,%1,%2,%3}, {%4,%5,%6,%7}, {%8,%9}, {%0,%1,%2,%3};"
                 : "+f"(c[0]), "+f"(c[1]), "+f"(c[2]), "+f"(c[3])
                 : "r"(a0), "r"(a1), "r"(a2), "r"(a3), "r"(b0), "r"(b1));
}

__device__ __forceinline__ void bf8_to_f(const uint4 u, float* f) {
    float2 a = __bfloat1622float2(*(const __nv_bfloat162*)&u.x);
    float2 b = __bfloat1622float2(*(const __nv_bfloat162*)&u.y);
    float2 c = __bfloat1622float2(*(const __nv_bfloat162*)&u.z);
    float2 d = __bfloat1622float2(*(const __nv_bfloat162*)&u.w);
    f[0] = a.x; f[1] = a.y; f[2] = b.x; f[3] = b.y;
    f[4] = c.x; f[5] = c.y; f[6] = d.x; f[7] = d.y;
}

__device__ __forceinline__ float gelu1(float x) {
    return 0.5f * x * (1.f + erff(x * 0.70710678118654752f));
}

__device__ __constant__ int c_rbase[4] = {0, N_OP, 3 * N_OP, 2 * N_OP};

// ---------------- tprep device helper (warp-parallel stats) ----------------
__device__ void tprep_body(int b, const float* __restrict__ Wt, const float* __restrict__ bt) {
    int t = threadIdx.x, w = t >> 5, lane = t & 31;
    if (b < 32) {
        int idx = b * 8 + w;
        int c = idx >> 4, d = idx & 15;
        float acc = 0.f;
        for (int i = lane; i < 256; i += 32) acc += Wt[i * 16 + c] * Wt[i * 16 + d];
#pragma unroll
        for (int o = 16; o; o >>= 1) acc += __shfl_xor_sync(0xffffffffu, acc, o);
        if (lane == 0) g_tstat[idx] = acc * (1.f / 256.f);
    } else if (b < 34) {
        int idx = (b - 32) * 8 + w;
        float a = 0.f, h = 0.f;
        for (int i = lane; i < 256; i += 32) {
            float wv = Wt[i * 16 + idx];
            a += wv; h += wv * bt[i];
        }
#pragma unroll
        for (int o = 16; o; o >>= 1) {
            a += __shfl_xor_sync(0xffffffffu, a, o);
            h += __shfl_xor_sync(0xffffffffu, h, o);
        }
        if (lane == 0) { g_tstat[256 + idx] = a * (1.f / 256.f); g_tstat[272 + idx] = h * (1.f / 256.f); }
    } else if (w == 0) {
        float c0 = 0.f, c1 = 0.f;
        for (int i = lane; i < 256; i += 32) { float v = bt[i]; c0 += v; c1 += v * v; }
#pragma unroll
        for (int o = 16; o; o >>= 1) {
            c0 += __shfl_xor_sync(0xffffffffu, c0, o);
            c1 += __shfl_xor_sync(0xffffffffu, c1, o);
        }
        if (lane == 0) { g_tstat[288] = c0 * (1.f / 256.f); g_tstat[289] = c1 * (1.f / 256.f); }
    }
}

// ---------------- L1: init/zero + tprep ----------------
__global__ void k_initzero(const float* __restrict__ x_op,
                           const float* __restrict__ Wt, const float* __restrict__ bt) {
    if (blockIdx.x >= NZB) { tprep_body(blockIdx.x - NZB, Wt, bt); return; }
    int i = blockIdx.x * blockDim.x + threadIdx.x;
    if (i < N_OP * DD / 4) ((float4*)g_x0)[i] = ((const float4*)x_op)[i];
    if (i < N_OP * 20 / 4) ((float4*)g_tacc)[i] = make_float4(0.f, 0.f, 0.f, 0.f);
    if (i < NCTR) g_cnt[i] = 0;
}

// ---------------- L2: temporal edge pass + CSR count ----------------
__global__ void k_temporal_count(const float* __restrict__ dtp,
                                 const int* e0, const int* e1, const int* e2, const int* e3,
                                 int E0, int E1, int E2, int E3, int bptT, int bpt) {
    if (blockIdx.x >= (unsigned)bptT) {   // count branch
        int bb = blockIdx.x - bptT;
        int ty = bb / bpt;
        const int* ei = (ty == 0) ? e0 : (ty == 1) ? e1 : (ty == 2) ? e2 : e3;
        int E = (ty == 0) ? E0 : (ty == 1) ? E1 : (ty == 2) ? E2 : E3;
        int idx = (bb - ty * bpt) * 256 + threadIdx.x;
        if (idx < E) atomicAdd(&g_cnt[c_rbase[ty] + ei[E + idx]], 1);
        return;
    }
    __shared__ float sG[256], sa[16], sh2[16], sc[2];
    int t = threadIdx.x;
    if (t < 256) sG[t] = g_tstat[t];
    if (t < 16) { sa[t] = g_tstat[256 + t]; sh2[t] = g_tstat[272 + t]; }
    if (t < 2) sc[t] = g_tstat[288 + t];
    __syncthreads();
    int e = blockIdx.x * blockDim.x + t;
    if (e >= E0) return;
    float dt = dtp[e];
    float temb[16];
#pragma unroll
    for (int j = 0; j < 8; j++) {
        float s, c;
        sincosf(dt * exp2f(-1.2457230355827609f * (float)j), &s, &c);
        temb[2 * j] = s; temb[2 * j + 1] = c;
    }
    float mu = sc[0], hs = 0.f, q = 0.f;
#pragma unroll
    for (int c = 0; c < 16; c++) {
        mu += sa[c] * temb[c];
        hs += sh2[c] * temb[c];
        float r = 0.f;
#pragma unroll
        for (int d = 0; d < 16; d++) r += sG[c * 16 + d] * temb[d];
        q += r * temb[c];
    }
    float var = q + 2.f * hs + sc[1] - mu * mu;
    float rs = rsqrtf(var + 1e-5f);
    int src = e0[e];
    float* acc = g_tacc + (size_t)src * 20;
    red_add_v4(acc + 0,  make_float4(rs * temb[0],  rs * temb[1],  rs * temb[2],  rs * temb[3]));
    red_add_v4(acc + 4,  make_float4(rs * temb[4],  rs * temb[5],  rs * temb[6],  rs * temb[7]));
    red_add_v4(acc + 8,  make_float4(rs * temb[8],  rs * temb[9],  rs * temb[10], rs * temb[11]));
    red_add_v4(acc + 12, make_float4(rs * temb[12], rs * temb[13], rs * temb[14], rs * temb[15]));
    red_add_v4(acc + 16, make_float4(rs, rs * mu, 1.f, 0.f));
}

// ---------------- L3: scan ----------------
__global__ void k_scan() {
    __shared__ int sp[1024];
    int arr = blockIdx.x, t = threadIdx.x;
    int base = (arr < 3) ? arr * N_OP : 3 * N_OP;
    int len = (arr < 3) ? N_OP : N_M;
    int chunk = (len + 1023) / 1024;
    int s0 = t * chunk, s1 = min(s0 + chunk, len);
    int sum = 0;
    for (int i = s0; i < s1; i++) sum += g_cnt[base + i];
    sp[t] = sum;
    __syncthreads();
    for (int o = 1; o < 1024; o <<= 1) {
        int v = (t >= o) ? sp[t - o] : 0;
        __syncthreads();
        sp[t] += v;
        __syncthreads();
    }
    int run = (t > 0) ? sp[t - 1] : 0;
    for (int i = s0; i < s1; i++) {
        g_off[base + i] = run;
        g_cur[base + i] = run;
        run += g_cnt[base + i];
    }
}

// ---------------- L4: tfinal + scatter + wstack (merged) ----------------
__global__ void k_prep4(const float* __restrict__ Wt, const float* __restrict__ bt,
                        const float* __restrict__ lng, const float* __restrict__ lnb,
                        const int* e0, const int* e1, const int* e2, const int* e3,
                        int E0, int E1, int E2, int E3, int bpt,
                        const float* __restrict__ Wk, const float* __restrict__ bk,
                        const float* __restrict__ Wq, const float* __restrict__ bq,
                        const float* __restrict__ Wv, const float* __restrict__ bv,
                        const float* __restrict__ a_rel, const float* __restrict__ m_rel) {
    if (blockIdx.x < N_OP) {             // tfinal
        __shared__ float s[20];
        int n = blockIdx.x, t = threadIdx.x;
        if (t < 20) s[t] = g_tacc[(size_t)n * 20 + t];
        __syncthreads();
        float cnt = s[18];
        if (cnt == 0.f) return;
        float sr = s[16], srm = s[17];
        const float4* wr = (const float4*)(Wt + t * 16);
        float4 w0 = wr[0], w1 = wr[1], w2 = wr[2], w3 = wr[3];
        float acc = w0.x * s[0] + w0.y * s[1] + w0.z * s[2] + w0.w * s[3]
                  + w1.x * s[4] + w1.y * s[5] + w1.z * s[6] + w1.w * s[7]
                  + w2.x * s[8] + w2.y * s[9] + w2.z * s[10] + w2.w * s[11]
                  + w3.x * s[12] + w3.y * s[13] + w3.z * s[14] + w3.w * s[15];
        float y = lng[t] * (acc + sr * bt[t] - srm) + cnt * lnb[t];
        g_x0[(size_t)n * DD + t] += y;
        return;
    }
    int bb = blockIdx.x - N_OP;
    if (bb < 4 * bpt) {                  // scatter
        int ty = bb / bpt;
        const int* ei = (ty == 0) ? e0 : (ty == 1) ? e1 : (ty == 2) ? e2 : e3;
        int E = (ty == 0) ? E0 : (ty == 1) ? E1 : (ty == 2) ? E2 : E3;
        int idx = (bb - ty * bpt) * 256 + threadIdx.x;
        if (idx >= E) return;
        int src = ei[idx], dst = ei[E + idx];
        int pos = atomicAdd(&g_cur[c_rbase[ty] + dst], 1);
        g_elist[ty * NE + pos] = src;
        return;
    }
    // wstack
    int row = bb - 4 * bpt;
    int in = threadIdx.x;
    float* wdst; float* bdst; int t;
    if (row < LD_OP) { wdst = g_wop; bdst = g_bop; t = 0; }
    else             { row -= LD_OP; wdst = g_wm; bdst = g_bm; t = 1; }
    int seg = row >> 8, o = row & 255;
    if (seg == 0) {
        wdst[row * DD + in] = Wq[t * 65536 + o * DD + in];
        if (in == 0) bdst[row] = bq[t * DD + o];
        return;
    }
    const float* rel; const float* Wb; const float* bb2; int e;
    if (t == 0) {
        if (seg <= 3) { e = seg - 1; rel = a_rel; Wb = Wk; bb2 = bk; }
        else          { e = seg - 4; rel = m_rel; Wb = Wv; bb2 = bv; }
    } else {
        e = 3;
        if (seg == 1) { rel = a_rel; Wb = Wk; bb2 = bk; }
        else          { rel = m_rel; Wb = Wv; bb2 = bv; }
    }
    int h = o >> 5, f = o & 31;
    const float* rp = rel + ((e * 8 + h) * 32) * 32 + f;
    const float* W = Wb + t * 65536 + (h * 32) * DD;
    float acc = 0.f;
#pragma unroll 8
    for (int d = 0; d < 32; d++) acc += rp[d * 32] * W[d * DD + in];
    wdst[row * DD + in] = acc;
    if (in == 0) {
        float bacc = 0.f;
        const float* b = bb2 + t * DD + h * 32;
        for (int d = 0; d < 32; d++) bacc += rp[d * 32] * b[d];
        bdst[row] = bacc;
    }
}

// ---------------- tf32 GEMM (vectorized-LDS mainloop), two configs per launch -------
__global__ void __launch_bounds__(256, 2)
k_gemm2(GemmCfg c0, GemmCfg c1, const float* __restrict__ skipP) {
    GemmCfg c = blockIdx.z ? c1 : c0;
    if (blockIdx.x >= (unsigned)c.gx || blockIdx.y >= (unsigned)c.gy) return;
    __shared__ unsigned sA[128][36];
    __shared__ unsigned sW[128][36];
    int tid = threadIdx.x;
    int lane = tid & 31, wid = tid >> 5;
    int gID = lane >> 2, tig = lane & 3;
    int mw = (wid >> 2) * 64, nw = (wid & 3) * 32;
    int m0 = blockIdx.y * 128, n0 = blockIdx.x * 128;
    int lr = tid >> 1;
    int lc0 = (tid & 1) * 16;
    float acc[4][4][4];
#pragma unroll
    for (int i = 0; i < 4; i++)
#pragma unroll
        for (int j = 0; j < 4; j++)
#pragma unroll
            for (int r = 0; r < 4; r++) acc[i][j][r] = 0.f;

    for (int k0 = 0; k0 < 256; k0 += 32) {
        int gm = m0 + lr;
#pragma unroll
        for (int j = 0; j < 4; j++) {
            int col = k0 + lc0 + j * 4;
            float4 v = make_float4(0.f, 0.f, 0.f, 0.f);
            if (gm < c.M) {
                v = *(const float4*)&c.A[(size_t)gm * c.lda + col];
                if (c.amode == 1) {
                    v.x = gelu1(v.x); v.y = gelu1(v.y);
                    v.z = gelu1(v.z); v.w = gelu1(v.w);
                }
            }
            *(uint4*)&sA[lr][lc0 + 4 * j] =
                make_uint4(f2tf32(v.x), f2tf32(v.y), f2tf32(v.z), f2tf32(v.w));
        }
#pragma unroll
        for (int j = 0; j < 4; j++) {
            float4 v = *(const float4*)&c.W[(size_t)(n0 + lr) * 256 + k0 + lc0 + j * 4];
            *(uint4*)&sW[lr][lc0 + 4 * j] =
                make_uint4(f2tf32(v.x), f2tf32(v.y), f2tf32(v.z), f2tf32(v.w));
        }
        __syncthreads();
        // k-remap: mma step s uses k = 4*c + s  (c = mma column 0..7)
        unsigned bv[4][2][4];
#pragma unroll
        for (int nt = 0; nt < 4; nt++) {
            int n = nw + nt * 8 + gID;
            *(uint4*)bv[nt][0] = *(const uint4*)&sW[n][4 * tig];
            *(uint4*)bv[nt][1] = *(const uint4*)&sW[n][4 * tig + 16];
        }
#pragma unroll
        for (int mt = 0; mt < 4; mt++) {
            int m = mw + mt * 16 + gID;
            unsigned av[4][4];
            *(uint4*)av[0] = *(const uint4*)&sA[m][4 * tig];
            *(uint4*)av[1] = *(const uint4*)&sA[m + 8][4 * tig];
            *(uint4*)av[2] = *(const uint4*)&sA[m][4 * tig + 16];
            *(uint4*)av[3] = *(const uint4*)&sA[m + 8][4 * tig + 16];
#pragma unroll
            for (int s = 0; s < 4; s++)
#pragma unroll
                for (int nt = 0; nt < 4; nt++)
                    mma_tf32(acc[mt][nt], av[0][s], av[1][s], av[2][s], av[3][s],
                             bv[nt][0][s], bv[nt][1][s]);
        }
        __syncthreads();
    }

    bool hs = (c.skipX != nullptr);
    float sa = 0.f, sb2 = 0.f;
    if (hs) { float s = skipP[c.skipIdx]; sa = 1.f / (1.f + __expf(-s)); sb2 = 1.f - sa; }
#pragma unroll
    for (int mt = 0; mt < 4; mt++) {
#pragma unroll
        for (int half = 0; half < 2; half++) {
            int m = m0 + mw + mt * 16 + gID + half * 8;
            if (m < c.M) {
#pragma unroll
                for (int nt = 0; nt < 4; nt++) {
                    int n = n0 + nw + nt * 8 + tig * 2;
                    float v0 = acc[mt][nt][half * 2 + 0] + c.bias[n];
                    float v1 = acc[mt][nt][half * 2 + 1] + c.bias[n + 1];
                    if (hs) {
                        v0 = sa * v0 + sb2 * c.skipX[(size_t)m * DD + n];
                        v1 = sa * v1 + sb2 * c.skipX[(size_t)m * DD + n + 1];
                    }
                    if (c.outBF) {
                        __nv_bfloat162* cp = (__nv_bfloat162*)((__nv_bfloat16*)c.C + (size_t)m * c.ldc + n);
                        *cp = __floats2bfloat162_rn(v0, v1);
                    } else {
                        *(float2*)((float*)c.C + (size_t)m * c.ldc + n) = make_float2(v0, v1);
                    }
                }
            }
        }
    }
}

// ---------------- CSR gather aggregation (index-preload + 2-way pipeline) -----------
__global__ void k_aggr(const float* __restrict__ prel) {
    __shared__ float sacc[8 * 256];
    __shared__ float sdn[64];
    int lane = threadIdx.x & 31, w = threadIdx.x >> 5;
    int head = lane >> 2;
    if (blockIdx.x < OPB) {
        int d = blockIdx.x * 8 + w;
        const uint4* qrow = (const uint4*)(g_proj_op + (size_t)d * LD_OP);
        float qf[8]; bf8_to_f(qrow[lane], qf);
        float outv[8] = {0.f, 0.f, 0.f, 0.f, 0.f, 0.f, 0.f, 0.f};
#pragma unroll
        for (int tt = 0; tt < 3; tt++) {
            int type = (tt == 2) ? 3 : tt;
            const __nv_bfloat16 *kp, *vp; int ld;
            if (tt == 0)      { kp = g_proj_op + 256; vp = g_proj_op + 1024; ld = LD_OP; }
            else if (tt == 1) { kp = g_proj_op + 512; vp = g_proj_op + 1280; ld = LD_OP; }
            else              { kp = g_proj_m + 256;  vp = g_proj_m + 512;   ld = LD_M; }
            float pr = prel[type * 8 + head] * SCALE;
            int rb = tt * N_OP + d;
            int s = g_off[rb], n = g_cnt[rb];
            const int* lst = g_elist + type * NE + s;
            float acc[8] = {0.f, 0.f, 0.f, 0.f, 0.f, 0.f, 0.f, 0.f};
            float dn = 0.f;
            for (int base = 0; base < n; base += 32) {
                int cnt = min(32, n - base);
                int myidx = (lane < cnt) ? lst[base + lane] : 0;
                int i = 0;
                for (; i + 1 < cnt; i += 2) {
                    int s0 = __shfl_sync(0xffffffffu, myidx, i);
                    int s1 = __shfl_sync(0xffffffffu, myidx, i + 1);
                    uint4 ku0 = *((const uint4*)(kp + (size_t)s0 * ld) + lane);
                    uint4 vu0 = *((const uint4*)(vp + (size_t)s0 * ld) + lane);
                    uint4 ku1 = *((const uint4*)(kp + (size_t)s1 * ld) + lane);
                    uint4 vu1 = *((const uint4*)(vp + (size_t)s1 * ld) + lane);
                    float kf[8], vf[8];
                    bf8_to_f(ku0, kf); bf8_to_f(vu0, vf);
                    float p = 0.f;
#pragma unroll
                    for (int j = 0; j < 8; j++) p += qf[j] * kf[j];
                    p += __shfl_xor_sync(0xffffffffu, p, 1);
                    p += __shfl_xor_sync(0xffffffffu, p, 2);
                    float ex = __expf(p * pr);
                    dn += ex;
#pragma unroll
                    for (int j = 0; j < 8; j++) acc[j] += vf[j] * ex;
                    bf8_to_f(ku1, kf); bf8_to_f(vu1, vf);
                    p = 0.f;
#pragma unroll
                    for (int j = 0; j < 8; j++) p += qf[j] * kf[j];
                    p += __shfl_xor_sync(0xffffffffu, p, 1);
                    p += __shfl_xor_sync(0xffffffffu, p, 2);
                    ex = __expf(p * pr);
                    dn += ex;
#pragma unroll
                    for (int j = 0; j < 8; j++) acc[j] += vf[j] * ex;
                }
                if (i < cnt) {
                    int s0 = __shfl_sync(0xffffffffu, myidx, i);
                    uint4 ku0 = *((const uint4*)(kp + (size_t)s0 * ld) + lane);
                    uint4 vu0 = *((const uint4*)(vp + (size_t)s0 * ld) + lane);
                    float kf[8], vf[8];
                    bf8_to_f(ku0, kf); bf8_to_f(vu0, vf);
                    float p = 0.f;
#pragma unroll
                    for (int j = 0; j < 8; j++) p += qf[j] * kf[j];
                    p += __shfl_xor_sync(0xffffffffu, p, 1);
                    p += __shfl_xor_sync(0xffffffffu, p, 2);
                    float ex = __expf(p * pr);
                    dn += ex;
#pragma unroll
                    for (int j = 0; j < 8; j++) acc[j] += vf[j] * ex;
                }
            }
            if (dn > 0.f) {
                float inv = 1.f / dn;
#pragma unroll
                for (int j = 0; j < 8; j++) outv[j] += acc[j] * inv;
            }
        }
        float* o = &g_out_op[(size_t)d * DD + lane * 8];
        *(float4*)o = make_float4(outv[0], outv[1], outv[2], outv[3]);
        *(float4*)(o + 4) = make_float4(outv[4], outv[5], outv[6], outv[7]);
    } else {
        int d = blockIdx.x - OPB;
        const uint4* qrow = (const uint4*)(g_proj_m + (size_t)d * LD_M);
        float qf[8]; bf8_to_f(qrow[lane], qf);
        float pr = prel[16 + head] * SCALE;
        int rb = 3 * N_OP + d;
        int s = g_off[rb], n = g_cnt[rb];
        const int* lst = g_elist + 2 * NE + s;
        int per = (n + 7) / 8;
        int i0 = w * per, i1 = min(i0 + per, n);
        float acc[8] = {0.f, 0.f, 0.f, 0.f, 0.f, 0.f, 0.f, 0.f};
        float dn = 0.f;
        for (int base = i0; base < i1; base += 32) {
            int cnt = min(32, i1 - base);
            int myidx = (lane < cnt) ? lst[base + lane] : 0;
            for (int i = 0; i < cnt; i++) {
                int src = __shfl_sync(0xffffffffu, myidx, i);
                uint4 ku = *((const uint4*)(g_proj_op + (size_t)src * LD_OP + 768) + lane);
                uint4 vu = *((const uint4*)(g_proj_op + (size_t)src * LD_OP + 1536) + lane);
                float kf[8], vf[8];
                bf8_to_f(ku, kf); bf8_to_f(vu, vf);
                float p = 0.f;
#pragma unroll
                for (int j = 0; j < 8; j++) p += qf[j] * kf[j];
                p += __shfl_xor_sync(0xffffffffu, p, 1);
                p += __shfl_xor_sync(0xffffffffu, p, 2);
                float ex = __expf(p * pr);
                dn += ex;
#pragma unroll
                for (int j = 0; j < 8; j++) acc[j] += vf[j] * ex;
            }
        }
#pragma unroll
        for (int j = 0; j < 8; j++) sacc[w * 256 + lane * 8 + j] = acc[j];
        if ((lane & 3) == 0) sdn[w * 8 + head] = dn;
        __syncthreads();
        int ch = threadIdx.x, hd = ch >> 5;
        float sv = 0.f, Dv = 0.f;
#pragma unroll
        for (int w2 = 0; w2 < 8; w2++) {
            sv += sacc[w2 * 256 + ch];
            Dv += sdn[w2 * 8 + hd];
        }
        g_out_m[(size_t)d * DD + ch] = (Dv > 0.f) ? sv / Dv : 0.f;
    }
}

// ---------------- launch ----------------
extern "C" void kernel_launch(void* const* d_in, const int* in_sizes, int n_in,
                              void* d_out, int out_size) {
    const float* x_op = (const float*)d_in[0];
    const float* x_m  = (const float*)d_in[1];
    const float* dtp  = (const float*)d_in[2];
    const int* ei_mp  = (const int*)d_in[3];
    const int* ei_pr  = (const int*)d_in[4];
    const int* ei_on  = (const int*)d_in[5];
    const int* ei_ho  = (const int*)d_in[6];
    const float* Wt   = (const float*)d_in[7];
    const float* bt   = (const float*)d_in[8];
    const float* lng  = (const float*)d_in[9];
    const float* lnb  = (const float*)d_in[10];
    const float* Wk   = (const float*)d_in[11];
    const float* bk   = (const float*)d_in[12];
    const float* Wq   = (const float*)d_in[13];
    const float* bq   = (const float*)d_in[14];
    const float* Wv   = (const float*)d_in[15];
    const float* bv   = (const float*)d_in[16];
    const float* Wa   = (const float*)d_in[17];
    const float* ba   = (const float*)d_in[18];
    const float* skip = (const float*)d_in[19];
    const float* a_rel = (const float*)d_in[20];
    const float* m_rel = (const float*)d_in[21];
    const float* p_rel = (const float*)d_in[22];
    float* out = (float*)d_out;

    float *p_x0, *p_wop, *p_bop, *p_wm, *p_bm, *p_oop, *p_om;
    __nv_bfloat16 *p_pop, *p_pm;
    cudaGetSymbolAddress((void**)&p_x0, g_x0);
    cudaGetSymbolAddress((void**)&p_pop, g_proj_op);
    cudaGetSymbolAddress((void**)&p_pm, g_proj_m);
    cudaGetSymbolAddress((void**)&p_wop, g_wop);
    cudaGetSymbolAddress((void**)&p_bop, g_bop);
    cudaGetSymbolAddress((void**)&p_wm, g_wm);
    cudaGetSymbolAddress((void**)&p_bm, g_bm);
    cudaGetSymbolAddress((void**)&p_oop, g_out_op);
    cudaGetSymbolAddress((void**)&p_om, g_out_m);

    int E0 = in_sizes[3] / 2, E1 = in_sizes[4] / 2, E2 = in_sizes[5] / 2, E3 = in_sizes[6] / 2;

    int Emax = E0;
    if (E1 > Emax) Emax = E1;
    if (E2 > Emax) Emax = E2;
    if (E3 > Emax) Emax = E3;
    int bpt = (Emax + 255) / 256;
    int bptT = (E0 + 255) / 256;

    // L1: init/zero + temporal stats
    k_initzero<<<NZB + 35, 256>>>(x_op, Wt, bt);
    // L2: temporal moment scatter + CSR count
    k_temporal_count<<<bptT + 4 * bpt, 256>>>(dtp, ei_mp, ei_pr, ei_on, ei_ho,
                                              E0, E1, E2, E3, bptT, bpt);
    // L3: CSR scan
    k_scan<<<4, 1024>>>();
    // L4: temporal finalize + CSR scatter + weight stacking
    k_prep4<<<N_OP + 4 * bpt + WSB, 256>>>(Wt, bt, lng, lnb,
                                           ei_mp, ei_pr, ei_on, ei_ho, E0, E1, E2, E3, bpt,
                                           Wk, bk, Wq, bq, Wv, bv, a_rel, m_rel);
    // L5: stacked projections (op + machine, bf16 out)
    {
        GemmCfg cOp = {p_x0, p_wop, p_bop, p_pop, N_OP, DD, LD_OP,
                       LD_OP / 128, (N_OP + 127) / 128, nullptr, 0, 1, 0};
        GemmCfg cM  = {x_m, p_wm, p_bm, p_pm, N_M, DD, LD_M,
                       LD_M / 128, (N_M + 127) / 128, nullptr, 0, 1, 0};
        k_gemm2<<<dim3(LD_OP / 128, (N_OP + 127) / 128, 2), 256>>>(cOp, cM, nullptr);
    }
    // L6: CSR gather aggregation
    k_aggr<<<OPB + N_M, 256>>>(p_rel);
    // L7: final GEMMs (GELU on load, gated skip, fp32 to d_out)
    {
        GemmCfg cOp = {p_oop, Wa, ba, out, N_OP, DD, DD,
                       2, (N_OP + 127) / 128, p_x0, 0, 0, 1};
        GemmCfg cM  = {p_om, Wa + 65536, ba + 256, out + (size_t)N_OP * DD, N_M, DD, DD,
                       2, (N_M + 127) / 128, x_m, 1, 0, 1};
        k_gemm2<<<dim3(2, (N_OP + 127) / 128, 2), 256>>>(cOp, cM, skip);
    }
}

// round 11
// speedup vs baseline: 1.1139x; 1.1139x over previous
#include <cuda_runtime.h>
#include <cuda_bf16.h>
#include <math.h>

#define N_OP 20000
#define N_M  500
#define NE   200000
#define DD   256
#define HH   8

#define LD_OP 1792   // [q | ka0 | ka1 | ka2 | va0 | va1 | va2]
#define LD_M  768    // [q | ka3 | va3]
#define OPB  2500
#define SCALE 0.17677669529663687f
#define NZB  5000    // initzero blocks
#define WSB  (LD_OP + LD_M)

// ---------------- scratch ----------------
__device__ float g_x0[N_OP * DD];
__device__ __nv_bfloat16 g_proj_op[(size_t)N_OP * LD_OP];
__device__ __nv_bfloat16 g_proj_m[N_M * LD_M];
__device__ float g_wop[LD_OP * DD];
__device__ float g_bop[LD_OP];
__device__ float g_wm[LD_M * DD];
__device__ float g_bm[LD_M];
__device__ float g_out_op[N_OP * DD];
__device__ float g_out_m[N_M * DD];
__device__ float g_tstat[300];
__device__ float g_tacc[N_OP * 20];
#define NCTR (3 * N_OP + N_M)
__device__ int g_cnt[NCTR];
__device__ int g_off[NCTR];
__device__ int g_cur[NCTR];
__device__ int g_elist[4 * NE];

struct GemmCfg {
    const float* A; const float* W; const float* bias; void* C;
    int M, lda, ldc, gx, gy;
    const float* skipX; int skipIdx; int outBF; int amode;
};

__device__ __forceinline__ void red_add_v4(float* p, float4 v) {
    asm volatile("red.global.add.v4.f32 [%0], {%1,%2,%3,%4};"
                 :: "l"(p), "f"(v.x), "f"(v.y), "f"(v.z), "f"(v.w) : "memory");
}

__device__ __forceinline__ unsigned f2tf32(float f) {
    unsigned u; asm("cvt.rna.tf32.f32 %0, %1;" : "=r"(u) : "f"(f)); return u;
}

__device__ __forceinline__ void mma_tf32(float* c, unsigned a0, unsigned a1,
                                         unsigned a2, unsigned a3,
                                         unsigned b0, unsigned b1) {
    asm volatile("mma.sync.aligned.m16n8k8.row.col.f32.tf32.tf32.f32 "
                 "{%0,%1,%2,%3}, {%4,%5,%6,%7}, {%8,%9}, {%0,%1,%2,%3};"
                 : "+f"(c[0]), "+f"(c[1]), "+f"(c[2]), "+f"(c[3])
                 : "r"(a0), "r"(a1), "r"(a2), "r"(a3), "r"(b0), "r"(b1));
}

__device__ __forceinline__ void bf8_to_f(const uint4 u, float* f) {
    float2 a = __bfloat1622float2(*(const __nv_bfloat162*)&u.x);
    float2 b = __bfloat1622float2(*(const __nv_bfloat162*)&u.y);
    float2 c = __bfloat1622float2(*(const __nv_bfloat162*)&u.z);
    float2 d = __bfloat1622float2(*(const __nv_bfloat162*)&u.w);
    f[0] = a.x; f[1] = a.y; f[2] = b.x; f[3] = b.y;
    f[4] = c.x; f[5] = c.y; f[6] = d.x; f[7] = d.y;
}

__device__ __forceinline__ float gelu1(float x) {
    return 0.5f * x * (1.f + erff(x * 0.70710678118654752f));
}

__device__ __constant__ int c_rbase[4] = {0, N_OP, 3 * N_OP, 2 * N_OP};

// ---------------- tprep device helper (warp-parallel stats) ----------------
__device__ void tprep_body(int b, const float* __restrict__ Wt, const float* __restrict__ bt) {
    int t = threadIdx.x, w = t >> 5, lane = t & 31;
    if (b < 32) {
        int idx = b * 8 + w;
        int c = idx >> 4, d = idx & 15;
        float acc = 0.f;
        for (int i = lane; i < 256; i += 32) acc += Wt[i * 16 + c] * Wt[i * 16 + d];
#pragma unroll
        for (int o = 16; o; o >>= 1) acc += __shfl_xor_sync(0xffffffffu, acc, o);
        if (lane == 0) g_tstat[idx] = acc * (1.f / 256.f);
    } else if (b < 34) {
        int idx = (b - 32) * 8 + w;
        float a = 0.f, h = 0.f;
        for (int i = lane; i < 256; i += 32) {
            float wv = Wt[i * 16 + idx];
            a += wv; h += wv * bt[i];
        }
#pragma unroll
        for (int o = 16; o; o >>= 1) {
            a += __shfl_xor_sync(0xffffffffu, a, o);
            h += __shfl_xor_sync(0xffffffffu, h, o);
        }
        if (lane == 0) { g_tstat[256 + idx] = a * (1.f / 256.f); g_tstat[272 + idx] = h * (1.f / 256.f); }
    } else if (w == 0) {
        float c0 = 0.f, c1 = 0.f;
        for (int i = lane; i < 256; i += 32) { float v = bt[i]; c0 += v; c1 += v * v; }
#pragma unroll
        for (int o = 16; o; o >>= 1) {
            c0 += __shfl_xor_sync(0xffffffffu, c0, o);
            c1 += __shfl_xor_sync(0xffffffffu, c1, o);
        }
        if (lane == 0) { g_tstat[288] = c0 * (1.f / 256.f); g_tstat[289] = c1 * (1.f / 256.f); }
    }
}

// ---------------- L1: init/zero + tprep ----------------
__global__ void k_initzero(const float* __restrict__ x_op,
                           const float* __restrict__ Wt, const float* __restrict__ bt) {
    if (blockIdx.x >= NZB) { tprep_body(blockIdx.x - NZB, Wt, bt); return; }
    int i = blockIdx.x * blockDim.x + threadIdx.x;
    if (i < N_OP * DD / 4) ((float4*)g_x0)[i] = ((const float4*)x_op)[i];
    if (i < N_OP * 20 / 4) ((float4*)g_tacc)[i] = make_float4(0.f, 0.f, 0.f, 0.f);
    if (i < NCTR) g_cnt[i] = 0;
}

// ---------------- L2: temporal edge pass + CSR count ----------------
__global__ void k_temporal_count(const float* __restrict__ dtp,
                                 const int* e0, const int* e1, const int* e2, const int* e3,
                                 int E0, int E1, int E2, int E3, int bptT, int bpt) {
    if (blockIdx.x >= (unsigned)bptT) {   // count branch
        int bb = blockIdx.x - bptT;
        int ty = bb / bpt;
        const int* ei = (ty == 0) ? e0 : (ty == 1) ? e1 : (ty == 2) ? e2 : e3;
        int E = (ty == 0) ? E0 : (ty == 1) ? E1 : (ty == 2) ? E2 : E3;
        int idx = (bb - ty * bpt) * 256 + threadIdx.x;
        if (idx < E) atomicAdd(&g_cnt[c_rbase[ty] + ei[E + idx]], 1);
        return;
    }
    __shared__ float sG[256], sa[16], sh2[16], sc[2];
    int t = threadIdx.x;
    if (t < 256) sG[t] = g_tstat[t];
    if (t < 16) { sa[t] = g_tstat[256 + t]; sh2[t] = g_tstat[272 + t]; }
    if (t < 2) sc[t] = g_tstat[288 + t];
    __syncthreads();
    int e = blockIdx.x * blockDim.x + t;
    if (e >= E0) return;
    float dt = dtp[e];
    float temb[16];
#pragma unroll
    for (int j = 0; j < 8; j++) {
        float s, c;
        sincosf(dt * exp2f(-1.2457230355827609f * (float)j), &s, &c);
        temb[2 * j] = s; temb[2 * j + 1] = c;
    }
    float mu = sc[0], hs = 0.f, q = 0.f;
#pragma unroll
    for (int c = 0; c < 16; c++) {
        mu += sa[c] * temb[c];
        hs += sh2[c] * temb[c];
        float r = 0.f;
#pragma unroll
        for (int d = 0; d < 16; d++) r += sG[c * 16 + d] * temb[d];
        q += r * temb[c];
    }
    float var = q + 2.f * hs + sc[1] - mu * mu;
    float rs = rsqrtf(var + 1e-5f);
    int src = e0[e];
    float* acc = g_tacc + (size_t)src * 20;
    red_add_v4(acc + 0,  make_float4(rs * temb[0],  rs * temb[1],  rs * temb[2],  rs * temb[3]));
    red_add_v4(acc + 4,  make_float4(rs * temb[4],  rs * temb[5],  rs * temb[6],  rs * temb[7]));
    red_add_v4(acc + 8,  make_float4(rs * temb[8],  rs * temb[9],  rs * temb[10], rs * temb[11]));
    red_add_v4(acc + 12, make_float4(rs * temb[12], rs * temb[13], rs * temb[14], rs * temb[15]));
    red_add_v4(acc + 16, make_float4(rs, rs * mu, 1.f, 0.f));
}

// ---------------- L3: scan ----------------
__global__ void k_scan() {
    __shared__ int sp[1024];
    int arr = blockIdx.x, t = threadIdx.x;
    int base = (arr < 3) ? arr * N_OP : 3 * N_OP;
    int len = (arr < 3) ? N_OP : N_M;
    int chunk = (len + 1023) / 1024;
    int s0 = t * chunk, s1 = min(s0 + chunk, len);
    int sum = 0;
    for (int i = s0; i < s1; i++) sum += g_cnt[base + i];
    sp[t] = sum;
    __syncthreads();
    for (int o = 1; o < 1024; o <<= 1) {
        int v = (t >= o) ? sp[t - o] : 0;
        __syncthreads();
        sp[t] += v;
        __syncthreads();
    }
    int run = (t > 0) ? sp[t - 1] : 0;
    for (int i = s0; i < s1; i++) {
        g_off[base + i] = run;
        g_cur[base + i] = run;
        run += g_cnt[base + i];
    }
}

// ---------------- L4: tfinal + scatter + wstack (merged) ----------------
__global__ void k_prep4(const float* __restrict__ Wt, const float* __restrict__ bt,
                        const float* __restrict__ lng, const float* __restrict__ lnb,
                        const int* e0, const int* e1, const int* e2, const int* e3,
                        int E0, int E1, int E2, int E3, int bpt,
                        const float* __restrict__ Wk, const float* __restrict__ bk,
                        const float* __restrict__ Wq, const float* __restrict__ bq,
                        const float* __restrict__ Wv, const float* __restrict__ bv,
                        const float* __restrict__ a_rel, const float* __restrict__ m_rel) {
    if (blockIdx.x < N_OP) {             // tfinal
        __shared__ float s[20];
        int n = blockIdx.x, t = threadIdx.x;
        if (t < 20) s[t] = g_tacc[(size_t)n * 20 + t];
        __syncthreads();
        float cnt = s[18];
        if (cnt == 0.f) return;
        float sr = s[16], srm = s[17];
        const float4* wr = (const float4*)(Wt + t * 16);
        float4 w0 = wr[0], w1 = wr[1], w2 = wr[2], w3 = wr[3];
        float acc = w0.x * s[0] + w0.y * s[1] + w0.z * s[2] + w0.w * s[3]
                  + w1.x * s[4] + w1.y * s[5] + w1.z * s[6] + w1.w * s[7]
                  + w2.x * s[8] + w2.y * s[9] + w2.z * s[10] + w2.w * s[11]
                  + w3.x * s[12] + w3.y * s[13] + w3.z * s[14] + w3.w * s[15];
        float y = lng[t] * (acc + sr * bt[t] - srm) + cnt * lnb[t];
        g_x0[(size_t)n * DD + t] += y;
        return;
    }
    int bb = blockIdx.x - N_OP;
    if (bb < 4 * bpt) {                  // scatter
        int ty = bb / bpt;
        const int* ei = (ty == 0) ? e0 : (ty == 1) ? e1 : (ty == 2) ? e2 : e3;
        int E = (ty == 0) ? E0 : (ty == 1) ? E1 : (ty == 2) ? E2 : E3;
        int idx = (bb - ty * bpt) * 256 + threadIdx.x;
        if (idx >= E) return;
        int src = ei[idx], dst = ei[E + idx];
        int pos = atomicAdd(&g_cur[c_rbase[ty] + dst], 1);
        g_elist[ty * NE + pos] = src;
        return;
    }
    // wstack
    int row = bb - 4 * bpt;
    int in = threadIdx.x;
    float* wdst; float* bdst; int t;
    if (row < LD_OP) { wdst = g_wop; bdst = g_bop; t = 0; }
    else             { row -= LD_OP; wdst = g_wm; bdst = g_bm; t = 1; }
    int seg = row >> 8, o = row & 255;
    if (seg == 0) {
        wdst[row * DD + in] = Wq[t * 65536 + o * DD + in];
        if (in == 0) bdst[row] = bq[t * DD + o];
        return;
    }
    const float* rel; const float* Wb; const float* bb2; int e;
    if (t == 0) {
        if (seg <= 3) { e = seg - 1; rel = a_rel; Wb = Wk; bb2 = bk; }
        else          { e = seg - 4; rel = m_rel; Wb = Wv; bb2 = bv; }
    } else {
        e = 3;
        if (seg == 1) { rel = a_rel; Wb = Wk; bb2 = bk; }
        else          { rel = m_rel; Wb = Wv; bb2 = bv; }
    }
    int h = o >> 5, f = o & 31;
    const float* rp = rel + ((e * 8 + h) * 32) * 32 + f;
    const float* W = Wb + t * 65536 + (h * 32) * DD;
    float acc = 0.f;
#pragma unroll 8
    for (int d = 0; d < 32; d++) acc += rp[d * 32] * W[d * DD + in];
    wdst[row * DD + in] = acc;
    if (in == 0) {
        float bacc = 0.f;
        const float* b = bb2 + t * DD + h * 32;
        for (int d = 0; d < 32; d++) bacc += rp[d * 32] * b[d];
        bdst[row] = bacc;
    }
}

// ---------------- tf32 GEMM (conflict-free scalar-LDS mainloop) ----------------
__global__ void __launch_bounds__(256, 2)
k_gemm2(GemmCfg c0, GemmCfg c1, const float* __restrict__ skipP) {
    GemmCfg c = blockIdx.z ? c1 : c0;
    if (blockIdx.x >= (unsigned)c.gx || blockIdx.y >= (unsigned)c.gy) return;
    __shared__ unsigned sA[128][36];
    __shared__ unsigned sW[128][36];
    int tid = threadIdx.x;
    int lane = tid & 31, wid = tid >> 5;
    int gID = lane >> 2, tig = lane & 3;
    int mw = (wid >> 2) * 64, nw = (wid & 3) * 32;
    int m0 = blockIdx.y * 128, n0 = blockIdx.x * 128;
    int lr = tid >> 1;
    int lc0 = (tid & 1) * 16;
    float acc[4][4][4];
#pragma unroll
    for (int i = 0; i < 4; i++)
#pragma unroll
        for (int j = 0; j < 4; j++)
#pragma unroll
            for (int r = 0; r < 4; r++) acc[i][j][r] = 0.f;

    for (int k0 = 0; k0 < 256; k0 += 32) {
        int gm = m0 + lr;
#pragma unroll
        for (int j = 0; j < 4; j++) {
            int col = k0 + lc0 + j * 4;
            float4 v = make_float4(0.f, 0.f, 0.f, 0.f);
            if (gm < c.M) {
                v = *(const float4*)&c.A[(size_t)gm * c.lda + col];
                if (c.amode == 1) {
                    v.x = gelu1(v.x); v.y = gelu1(v.y);
                    v.z = gelu1(v.z); v.w = gelu1(v.w);
                }
            }
            sA[lr][lc0 + 4 * j + 0] = f2tf32(v.x);
            sA[lr][lc0 + 4 * j + 1] = f2tf32(v.y);
            sA[lr][lc0 + 4 * j + 2] = f2tf32(v.z);
            sA[lr][lc0 + 4 * j + 3] = f2tf32(v.w);
        }
#pragma unroll
        for (int j = 0; j < 4; j++) {
            float4 v = *(const float4*)&c.W[(size_t)(n0 + lr) * 256 + k0 + lc0 + j * 4];
            sW[lr][lc0 + 4 * j + 0] = f2tf32(v.x);
            sW[lr][lc0 + 4 * j + 1] = f2tf32(v.y);
            sW[lr][lc0 + 4 * j + 2] = f2tf32(v.z);
            sW[lr][lc0 + 4 * j + 3] = f2tf32(v.w);
        }
        __syncthreads();
#pragma unroll
        for (int kk = 0; kk < 32; kk += 8) {
            unsigned bfr[4][2];
#pragma unroll
            for (int nt = 0; nt < 4; nt++) {
                int n = nw + nt * 8 + gID;
                bfr[nt][0] = sW[n][kk + tig];
                bfr[nt][1] = sW[n][kk + tig + 4];
            }
#pragma unroll
            for (int mt = 0; mt < 4; mt++) {
                int m = mw + mt * 16 + gID;
                unsigned a0 = sA[m][kk + tig];
                unsigned a1 = sA[m + 8][kk + tig];
                unsigned a2 = sA[m][kk + tig + 4];
                unsigned a3 = sA[m + 8][kk + tig + 4];
#pragma unroll
                for (int nt = 0; nt < 4; nt++)
                    mma_tf32(acc[mt][nt], a0, a1, a2, a3, bfr[nt][0], bfr[nt][1]);
            }
        }
        __syncthreads();
    }

    bool hs = (c.skipX != nullptr);
    float sa = 0.f, sb2 = 0.f;
    if (hs) { float s = skipP[c.skipIdx]; sa = 1.f / (1.f + __expf(-s)); sb2 = 1.f - sa; }
#pragma unroll
    for (int mt = 0; mt < 4; mt++) {
#pragma unroll
        for (int half = 0; half < 2; half++) {
            int m = m0 + mw + mt * 16 + gID + half * 8;
            if (m < c.M) {
#pragma unroll
                for (int nt = 0; nt < 4; nt++) {
                    int n = n0 + nw + nt * 8 + tig * 2;
                    float v0 = acc[mt][nt][half * 2 + 0] + c.bias[n];
                    float v1 = acc[mt][nt][half * 2 + 1] + c.bias[n + 1];
                    if (hs) {
                        v0 = sa * v0 + sb2 * c.skipX[(size_t)m * DD + n];
                        v1 = sa * v1 + sb2 * c.skipX[(size_t)m * DD + n + 1];
                    }
                    if (c.outBF) {
                        __nv_bfloat162* cp = (__nv_bfloat162*)((__nv_bfloat16*)c.C + (size_t)m * c.ldc + n);
                        *cp = __floats2bfloat162_rn(v0, v1);
                    } else {
                        *(float2*)((float*)c.C + (size_t)m * c.ldc + n) = make_float2(v0, v1);
                    }
                }
            }
        }
    }
}

// ---------------- CSR gather aggregation (index-preload + 2-way pipeline) -----------
__global__ void k_aggr(const float* __restrict__ prel) {
    __shared__ float sacc[8 * 256];
    __shared__ float sdn[64];
    int lane = threadIdx.x & 31, w = threadIdx.x >> 5;
    int head = lane >> 2;
    if (blockIdx.x < OPB) {
        int d = blockIdx.x * 8 + w;
        const uint4* qrow = (const uint4*)(g_proj_op + (size_t)d * LD_OP);
        float qf[8]; bf8_to_f(qrow[lane], qf);
        float outv[8] = {0.f, 0.f, 0.f, 0.f, 0.f, 0.f, 0.f, 0.f};
#pragma unroll
        for (int tt = 0; tt < 3; tt++) {
            int type = (tt == 2) ? 3 : tt;
            const __nv_bfloat16 *kp, *vp; int ld;
            if (tt == 0)      { kp = g_proj_op + 256; vp = g_proj_op + 1024; ld = LD_OP; }
            else if (tt == 1) { kp = g_proj_op + 512; vp = g_proj_op + 1280; ld = LD_OP; }
            else              { kp = g_proj_m + 256;  vp = g_proj_m + 512;   ld = LD_M; }
            float pr = prel[type * 8 + head] * SCALE;
            int rb = tt * N_OP + d;
            int s = g_off[rb], n = g_cnt[rb];
            const int* lst = g_elist + type * NE + s;
            float acc[8] = {0.f, 0.f, 0.f, 0.f, 0.f, 0.f, 0.f, 0.f};
            float dn = 0.f;
            for (int base = 0; base < n; base += 32) {
                int cnt = min(32, n - base);
                int myidx = (lane < cnt) ? lst[base + lane] : 0;
                int i = 0;
                for (; i + 1 < cnt; i += 2) {
                    int s0 = __shfl_sync(0xffffffffu, myidx, i);
                    int s1 = __shfl_sync(0xffffffffu, myidx, i + 1);
                    uint4 ku0 = *((const uint4*)(kp + (size_t)s0 * ld) + lane);
                    uint4 vu0 = *((const uint4*)(vp + (size_t)s0 * ld) + lane);
                    uint4 ku1 = *((const uint4*)(kp + (size_t)s1 * ld) + lane);
                    uint4 vu1 = *((const uint4*)(vp + (size_t)s1 * ld) + lane);
                    float kf[8], vf[8];
                    bf8_to_f(ku0, kf); bf8_to_f(vu0, vf);
                    float p = 0.f;
#pragma unroll
                    for (int j = 0; j < 8; j++) p += qf[j] * kf[j];
                    p += __shfl_xor_sync(0xffffffffu, p, 1);
                    p += __shfl_xor_sync(0xffffffffu, p, 2);
                    float ex = __expf(p * pr);
                    dn += ex;
#pragma unroll
                    for (int j = 0; j < 8; j++) acc[j] += vf[j] * ex;
                    bf8_to_f(ku1, kf); bf8_to_f(vu1, vf);
                    p = 0.f;
#pragma unroll
                    for (int j = 0; j < 8; j++) p += qf[j] * kf[j];
                    p += __shfl_xor_sync(0xffffffffu, p, 1);
                    p += __shfl_xor_sync(0xffffffffu, p, 2);
                    ex = __expf(p * pr);
                    dn += ex;
#pragma unroll
                    for (int j = 0; j < 8; j++) acc[j] += vf[j] * ex;
                }
                if (i < cnt) {
                    int s0 = __shfl_sync(0xffffffffu, myidx, i);
                    uint4 ku0 = *((const uint4*)(kp + (size_t)s0 * ld) + lane);
                    uint4 vu0 = *((const uint4*)(vp + (size_t)s0 * ld) + lane);
                    float kf[8], vf[8];
                    bf8_to_f(ku0, kf); bf8_to_f(vu0, vf);
                    float p = 0.f;
#pragma unroll
                    for (int j = 0; j < 8; j++) p += qf[j] * kf[j];
                    p += __shfl_xor_sync(0xffffffffu, p, 1);
                    p += __shfl_xor_sync(0xffffffffu, p, 2);
                    float ex = __expf(p * pr);
                    dn += ex;
#pragma unroll
                    for (int j = 0; j < 8; j++) acc[j] += vf[j] * ex;
                }
            }
            if (dn > 0.f) {
                float inv = 1.f / dn;
#pragma unroll
                for (int j = 0; j < 8; j++) outv[j] += acc[j] * inv;
            }
        }
        float* o = &g_out_op[(size_t)d * DD + lane * 8];
        *(float4*)o = make_float4(outv[0], outv[1], outv[2], outv[3]);
        *(float4*)(o + 4) = make_float4(outv[4], outv[5], outv[6], outv[7]);
    } else {
        int d = blockIdx.x - OPB;
        const uint4* qrow = (const uint4*)(g_proj_m + (size_t)d * LD_M);
        float qf[8]; bf8_to_f(qrow[lane], qf);
        float pr = prel[16 + head] * SCALE;
        int rb = 3 * N_OP + d;
        int s = g_off[rb], n = g_cnt[rb];
        const int* lst = g_elist + 2 * NE + s;
        int per = (n + 7) / 8;
        int i0 = w * per, i1 = min(i0 + per, n);
        float acc[8] = {0.f, 0.f, 0.f, 0.f, 0.f, 0.f, 0.f, 0.f};
        float dn = 0.f;
        for (int base = i0; base < i1; base += 32) {
            int cnt = min(32, i1 - base);
            int myidx = (lane < cnt) ? lst[base + lane] : 0;
            for (int i = 0; i < cnt; i++) {
                int src = __shfl_sync(0xffffffffu, myidx, i);
                uint4 ku = *((const uint4*)(g_proj_op + (size_t)src * LD_OP + 768) + lane);
                uint4 vu = *((const uint4*)(g_proj_op + (size_t)src * LD_OP + 1536) + lane);
                float kf[8], vf[8];
                bf8_to_f(ku, kf); bf8_to_f(vu, vf);
                float p = 0.f;
#pragma unroll
                for (int j = 0; j < 8; j++) p += qf[j] * kf[j];
                p += __shfl_xor_sync(0xffffffffu, p, 1);
                p += __shfl_xor_sync(0xffffffffu, p, 2);
                float ex = __expf(p * pr);
                dn += ex;
#pragma unroll
                for (int j = 0; j < 8; j++) acc[j] += vf[j] * ex;
            }
        }
#pragma unroll
        for (int j = 0; j < 8; j++) sacc[w * 256 + lane * 8 + j] = acc[j];
        if ((lane & 3) == 0) sdn[w * 8 + head] = dn;
        __syncthreads();
        int ch = threadIdx.x, hd = ch >> 5;
        float sv = 0.f, Dv = 0.f;
#pragma unroll
        for (int w2 = 0; w2 < 8; w2++) {
            sv += sacc[w2 * 256 + ch];
            Dv += sdn[w2 * 8 + hd];
        }
        g_out_m[(size_t)d * DD + ch] = (Dv > 0.f) ? sv / Dv : 0.f;
    }
}

// ---------------- launch ----------------
extern "C" void kernel_launch(void* const* d_in, const int* in_sizes, int n_in,
                              void* d_out, int out_size) {
    const float* x_op = (const float*)d_in[0];
    const float* x_m  = (const float*)d_in[1];
    const float* dtp  = (const float*)d_in[2];
    const int* ei_mp  = (const int*)d_in[3];
    const int* ei_pr  = (const int*)d_in[4];
    const int* ei_on  = (const int*)d_in[5];
    const int* ei_ho  = (const int*)d_in[6];
    const float* Wt   = (const float*)d_in[7];
    const float* bt   = (const float*)d_in[8];
    const float* lng  = (const float*)d_in[9];
    const float* lnb  = (const float*)d_in[10];
    const float* Wk   = (const float*)d_in[11];
    const float* bk   = (const float*)d_in[12];
    const float* Wq   = (const float*)d_in[13];
    const float* bq   = (const float*)d_in[14];
    const float* Wv   = (const float*)d_in[15];
    const float* bv   = (const float*)d_in[16];
    const float* Wa   = (const float*)d_in[17];
    const float* ba   = (const float*)d_in[18];
    const float* skip = (const float*)d_in[19];
    const float* a_rel = (const float*)d_in[20];
    const float* m_rel = (const float*)d_in[21];
    const float* p_rel = (const float*)d_in[22];
    float* out = (float*)d_out;

    float *p_x0, *p_wop, *p_bop, *p_wm, *p_bm, *p_oop, *p_om;
    __nv_bfloat16 *p_pop, *p_pm;
    cudaGetSymbolAddress((void**)&p_x0, g_x0);
    cudaGetSymbolAddress((void**)&p_pop, g_proj_op);
    cudaGetSymbolAddress((void**)&p_pm, g_proj_m);
    cudaGetSymbolAddress((void**)&p_wop, g_wop);
    cudaGetSymbolAddress((void**)&p_bop, g_bop);
    cudaGetSymbolAddress((void**)&p_wm, g_wm);
    cudaGetSymbolAddress((void**)&p_bm, g_bm);
    cudaGetSymbolAddress((void**)&p_oop, g_out_op);
    cudaGetSymbolAddress((void**)&p_om, g_out_m);

    int E0 = in_sizes[3] / 2, E1 = in_sizes[4] / 2, E2 = in_sizes[5] / 2, E3 = in_sizes[6] / 2;

    int Emax = E0;
    if (E1 > Emax) Emax = E1;
    if (E2 > Emax) Emax = E2;
    if (E3 > Emax) Emax = E3;
    int bpt = (Emax + 255) / 256;
    int bptT = (E0 + 255) / 256;

    // L1: init/zero + temporal stats
    k_initzero<<<NZB + 35, 256>>>(x_op, Wt, bt);
    // L2: temporal moment scatter + CSR count
    k_temporal_count<<<bptT + 4 * bpt, 256>>>(dtp, ei_mp, ei_pr, ei_on, ei_ho,
                                              E0, E1, E2, E3, bptT, bpt);
    // L3: CSR scan
    k_scan<<<4, 1024>>>();
    // L4: temporal finalize + CSR scatter + weight stacking
    k_prep4<<<N_OP + 4 * bpt + WSB, 256>>>(Wt, bt, lng, lnb,
                                           ei_mp, ei_pr, ei_on, ei_ho, E0, E1, E2, E3, bpt,
                                           Wk, bk, Wq, bq, Wv, bv, a_rel, m_rel);
    // L5: stacked projections (op + machine, bf16 out)
    {
        GemmCfg cOp = {p_x0, p_wop, p_bop, p_pop, N_OP, DD, LD_OP,
                       LD_OP / 128, (N_OP + 127) / 128, nullptr, 0, 1, 0};
        GemmCfg cM  = {x_m, p_wm, p_bm, p_pm, N_M, DD, LD_M,
                       LD_M / 128, (N_M + 127) / 128, nullptr, 0, 1, 0};
        k_gemm2<<<dim3(LD_OP / 128, (N_OP + 127) / 128, 2), 256>>>(cOp, cM, nullptr);
    }
    // L6: CSR gather aggregation
    k_aggr<<<OPB + N_M, 256>>>(p_rel);
    // L7: final GEMMs (GELU on load, gated skip, fp32 to d_out)
    {
        GemmCfg cOp = {p_oop, Wa, ba, out, N_OP, DD, DD,
                       2, (N_OP + 127) / 128, p_x0, 0, 0, 1};
        GemmCfg cM  = {p_om, Wa + 65536, ba + 256, out + (size_t)N_OP * DD, N_M, DD, DD,
                       2, (N_M + 127) / 128, x_m, 1, 0, 1};
        k_gemm2<<<dim3(2, (N_OP + 127) / 128, 2), 256>>>(cOp, cM, skip);
    }
}

// round 12
// speedup vs baseline: 1.1605x; 1.0419x over previous
#include <cuda_runtime.h>
#include <cuda_bf16.h>
#include <math.h>

#define N_OP 20000
#define N_M  500
#define NE   200000
#define DD   256
#define HH   8

#define LD_OP 1792   // [q | ka0 | ka1 | ka2 | va0 | va1 | va2]
#define LD_M  768    // [q | ka3 | va3]
#define OPB  2500
#define SCALE 0.17677669529663687f
#define NZB  5000    // initzero blocks
#define WSB  (LD_OP + LD_M)
#define TFB  200     // batched-tfinal blocks
#define TFN  100     // nodes per tfinal block

// ---------------- scratch ----------------
__device__ float g_x0[N_OP * DD];
__device__ __nv_bfloat16 g_proj_op[(size_t)N_OP * LD_OP];
__device__ __nv_bfloat16 g_proj_m[N_M * LD_M];
__device__ float g_wop[LD_OP * DD];
__device__ float g_bop[LD_OP];
__device__ float g_wm[LD_M * DD];
__device__ float g_bm[LD_M];
__device__ float g_out_op[N_OP * DD];
__device__ float g_out_m[N_M * DD];
__device__ float g_tstat[300];
__device__ float g_tacc[N_OP * 20];
#define NCTR (3 * N_OP + N_M)
__device__ int g_cnt[NCTR];
__device__ int g_off[NCTR];
__device__ int g_cur[NCTR];
__device__ int g_elist[4 * NE];

struct GemmCfg {
    const float* A; const float* W; const float* bias; void* C;
    int M, lda, ldc, gx, gy;
    const float* skipX; int skipIdx; int outBF; int amode;
};

__device__ __forceinline__ void red_add_v4(float* p, float4 v) {
    asm volatile("red.global.add.v4.f32 [%0], {%1,%2,%3,%4};"
                 :: "l"(p), "f"(v.x), "f"(v.y), "f"(v.z), "f"(v.w) : "memory");
}

__device__ __forceinline__ unsigned f2tf32(float f) {
    unsigned u; asm("cvt.rna.tf32.f32 %0, %1;" : "=r"(u) : "f"(f)); return u;
}

__device__ __forceinline__ void mma_tf32(float* c, unsigned a0, unsigned a1,
                                         unsigned a2, unsigned a3,
                                         unsigned b0, unsigned b1) {
    asm volatile("mma.sync.aligned.m16n8k8.row.col.f32.tf32.tf32.f32 "
                 "{%0,%1,%2,%3}, {%4,%5,%6,%7}, {%8,%9}, {%0,%1,%2,%3};"
                 : "+f"(c[0]), "+f"(c[1]), "+f"(c[2]), "+f"(c[3])
                 : "r"(a0), "r"(a1), "r"(a2), "r"(a3), "r"(b0), "r"(b1));
}

__device__ __forceinline__ void bf8_to_f(const uint4 u, float* f) {
    float2 a = __bfloat1622float2(*(const __nv_bfloat162*)&u.x);
    float2 b = __bfloat1622float2(*(const __nv_bfloat162*)&u.y);
    float2 c = __bfloat1622float2(*(const __nv_bfloat162*)&u.z);
    float2 d = __bfloat1622float2(*(const __nv_bfloat162*)&u.w);
    f[0] = a.x; f[1] = a.y; f[2] = b.x; f[3] = b.y;
    f[4] = c.x; f[5] = c.y; f[6] = d.x; f[7] = d.y;
}

__device__ __forceinline__ float gelu1(float x) {
    return 0.5f * x * (1.f + erff(x * 0.70710678118654752f));
}

__device__ __constant__ int c_rbase[4] = {0, N_OP, 3 * N_OP, 2 * N_OP};

// ---------------- tprep device helper (warp-parallel stats) ----------------
__device__ void tprep_body(int b, const float* __restrict__ Wt, const float* __restrict__ bt) {
    int t = threadIdx.x, w = t >> 5, lane = t & 31;
    if (b < 32) {
        int idx = b * 8 + w;
        int c = idx >> 4, d = idx & 15;
        float acc = 0.f;
        for (int i = lane; i < 256; i += 32) acc += Wt[i * 16 + c] * Wt[i * 16 + d];
#pragma unroll
        for (int o = 16; o; o >>= 1) acc += __shfl_xor_sync(0xffffffffu, acc, o);
        if (lane == 0) g_tstat[idx] = acc * (1.f / 256.f);
    } else if (b < 34) {
        int idx = (b - 32) * 8 + w;
        float a = 0.f, h = 0.f;
        for (int i = lane; i < 256; i += 32) {
            float wv = Wt[i * 16 + idx];
            a += wv; h += wv * bt[i];
        }
#pragma unroll
        for (int o = 16; o; o >>= 1) {
            a += __shfl_xor_sync(0xffffffffu, a, o);
            h += __shfl_xor_sync(0xffffffffu, h, o);
        }
        if (lane == 0) { g_tstat[256 + idx] = a * (1.f / 256.f); g_tstat[272 + idx] = h * (1.f / 256.f); }
    } else if (w == 0) {
        float c0 = 0.f, c1 = 0.f;
        for (int i = lane; i < 256; i += 32) { float v = bt[i]; c0 += v; c1 += v * v; }
#pragma unroll
        for (int o = 16; o; o >>= 1) {
            c0 += __shfl_xor_sync(0xffffffffu, c0, o);
            c1 += __shfl_xor_sync(0xffffffffu, c1, o);
        }
        if (lane == 0) { g_tstat[288] = c0 * (1.f / 256.f); g_tstat[289] = c1 * (1.f / 256.f); }
    }
}

// ---------------- L1: init/zero + tprep ----------------
__global__ void k_initzero(const float* __restrict__ x_op,
                           const float* __restrict__ Wt, const float* __restrict__ bt) {
    if (blockIdx.x >= NZB) { tprep_body(blockIdx.x - NZB, Wt, bt); return; }
    int i = blockIdx.x * blockDim.x + threadIdx.x;
    if (i < N_OP * DD / 4) ((float4*)g_x0)[i] = ((const float4*)x_op)[i];
    if (i < N_OP * 20 / 4) ((float4*)g_tacc)[i] = make_float4(0.f, 0.f, 0.f, 0.f);
    if (i < NCTR) g_cnt[i] = 0;
}

// ---------------- L2: temporal edge pass + CSR count ----------------
__global__ void k_temporal_count(const float* __restrict__ dtp,
                                 const int* e0, const int* e1, const int* e2, const int* e3,
                                 int E0, int E1, int E2, int E3, int bptT, int bpt) {
    if (blockIdx.x >= (unsigned)bptT) {   // count branch
        int bb = blockIdx.x - bptT;
        int ty = bb / bpt;
        const int* ei = (ty == 0) ? e0 : (ty == 1) ? e1 : (ty == 2) ? e2 : e3;
        int E = (ty == 0) ? E0 : (ty == 1) ? E1 : (ty == 2) ? E2 : E3;
        int idx = (bb - ty * bpt) * 256 + threadIdx.x;
        if (idx < E) atomicAdd(&g_cnt[c_rbase[ty] + ei[E + idx]], 1);
        return;
    }
    __shared__ float sG[256], sa[16], sh2[16], sc[2];
    int t = threadIdx.x;
    if (t < 256) sG[t] = g_tstat[t];
    if (t < 16) { sa[t] = g_tstat[256 + t]; sh2[t] = g_tstat[272 + t]; }
    if (t < 2) sc[t] = g_tstat[288 + t];
    __syncthreads();
    int e = blockIdx.x * blockDim.x + t;
    if (e >= E0) return;
    float dt = dtp[e];
    float temb[16];
#pragma unroll
    for (int j = 0; j < 8; j++) {
        float s, c;
        sincosf(dt * exp2f(-1.2457230355827609f * (float)j), &s, &c);
        temb[2 * j] = s; temb[2 * j + 1] = c;
    }
    float mu = sc[0], hs = 0.f, q = 0.f;
#pragma unroll
    for (int c = 0; c < 16; c++) {
        mu += sa[c] * temb[c];
        hs += sh2[c] * temb[c];
        float r = 0.f;
#pragma unroll
        for (int d = 0; d < 16; d++) r += sG[c * 16 + d] * temb[d];
        q += r * temb[c];
    }
    float var = q + 2.f * hs + sc[1] - mu * mu;
    float rs = rsqrtf(var + 1e-5f);
    int src = e0[e];
    float* acc = g_tacc + (size_t)src * 20;
    red_add_v4(acc + 0,  make_float4(rs * temb[0],  rs * temb[1],  rs * temb[2],  rs * temb[3]));
    red_add_v4(acc + 4,  make_float4(rs * temb[4],  rs * temb[5],  rs * temb[6],  rs * temb[7]));
    red_add_v4(acc + 8,  make_float4(rs * temb[8],  rs * temb[9],  rs * temb[10], rs * temb[11]));
    red_add_v4(acc + 12, make_float4(rs * temb[12], rs * temb[13], rs * temb[14], rs * temb[15]));
    red_add_v4(acc + 16, make_float4(rs, rs * mu, 1.f, 0.f));
}

// ---------------- L3: scan ----------------
__global__ void k_scan() {
    __shared__ int sp[1024];
    int arr = blockIdx.x, t = threadIdx.x;
    int base = (arr < 3) ? arr * N_OP : 3 * N_OP;
    int len = (arr < 3) ? N_OP : N_M;
    int chunk = (len + 1023) / 1024;
    int s0 = t * chunk, s1 = min(s0 + chunk, len);
    int sum = 0;
    for (int i = s0; i < s1; i++) sum += g_cnt[base + i];
    sp[t] = sum;
    __syncthreads();
    for (int o = 1; o < 1024; o <<= 1) {
        int v = (t >= o) ? sp[t - o] : 0;
        __syncthreads();
        sp[t] += v;
        __syncthreads();
    }
    int run = (t > 0) ? sp[t - 1] : 0;
    for (int i = s0; i < s1; i++) {
        g_off[base + i] = run;
        g_cur[base + i] = run;
        run += g_cnt[base + i];
    }
}

// ---------------- L4: batched tfinal + scatter + wstack (merged) ----------------
__global__ void k_prep4(const float* __restrict__ Wt, const float* __restrict__ bt,
                        const float* __restrict__ lng, const float* __restrict__ lnb,
                        const int* e0, const int* e1, const int* e2, const int* e3,
                        int E0, int E1, int E2, int E3, int bpt,
                        const float* __restrict__ Wk, const float* __restrict__ bk,
                        const float* __restrict__ Wq, const float* __restrict__ bq,
                        const float* __restrict__ Wv, const float* __restrict__ bv,
                        const float* __restrict__ a_rel, const float* __restrict__ m_rel) {
    if (blockIdx.x < TFB) {              // batched tfinal: TFN nodes per block
        __shared__ float s[20];
        int t = threadIdx.x;
        // per-thread channel constants (loaded once)
        const float4* wr = (const float4*)(Wt + t * 16);
        float4 w0 = wr[0], w1 = wr[1], w2 = wr[2], w3 = wr[3];
        float btv = bt[t], gv = lng[t], bv2 = lnb[t];
        int n0 = blockIdx.x * TFN;
        for (int ni = 0; ni < TFN; ni++) {
            int n = n0 + ni;
            if (t < 20) s[t] = g_tacc[(size_t)n * 20 + t];
            __syncthreads();
            float cnt = s[18];
            if (cnt != 0.f) {
                float sr = s[16], srm = s[17];
                float acc = w0.x * s[0] + w0.y * s[1] + w0.z * s[2] + w0.w * s[3]
                          + w1.x * s[4] + w1.y * s[5] + w1.z * s[6] + w1.w * s[7]
                          + w2.x * s[8] + w2.y * s[9] + w2.z * s[10] + w2.w * s[11]
                          + w3.x * s[12] + w3.y * s[13] + w3.z * s[14] + w3.w * s[15];
                float y = gv * (acc + sr * btv - srm) + cnt * bv2;
                g_x0[(size_t)n * DD + t] += y;
            }
            __syncthreads();
        }
        return;
    }
    int bb = blockIdx.x - TFB;
    if (bb < 4 * bpt) {                  // scatter
        int ty = bb / bpt;
        const int* ei = (ty == 0) ? e0 : (ty == 1) ? e1 : (ty == 2) ? e2 : e3;
        int E = (ty == 0) ? E0 : (ty == 1) ? E1 : (ty == 2) ? E2 : E3;
        int idx = (bb - ty * bpt) * 256 + threadIdx.x;
        if (idx >= E) return;
        int src = ei[idx], dst = ei[E + idx];
        int pos = atomicAdd(&g_cur[c_rbase[ty] + dst], 1);
        g_elist[ty * NE + pos] = src;
        return;
    }
    // wstack
    int row = bb - 4 * bpt;
    int in = threadIdx.x;
    float* wdst; float* bdst; int t;
    if (row < LD_OP) { wdst = g_wop; bdst = g_bop; t = 0; }
    else             { row -= LD_OP; wdst = g_wm; bdst = g_bm; t = 1; }
    int seg = row >> 8, o = row & 255;
    if (seg == 0) {
        wdst[row * DD + in] = Wq[t * 65536 + o * DD + in];
        if (in == 0) bdst[row] = bq[t * DD + o];
        return;
    }
    const float* rel; const float* Wb; const float* bb2; int e;
    if (t == 0) {
        if (seg <= 3) { e = seg - 1; rel = a_rel; Wb = Wk; bb2 = bk; }
        else          { e = seg - 4; rel = m_rel; Wb = Wv; bb2 = bv; }
    } else {
        e = 3;
        if (seg == 1) { rel = a_rel; Wb = Wk; bb2 = bk; }
        else          { rel = m_rel; Wb = Wv; bb2 = bv; }
    }
    int h = o >> 5, f = o & 31;
    const float* rp = rel + ((e * 8 + h) * 32) * 32 + f;
    const float* W = Wb + t * 65536 + (h * 32) * DD;
    float acc = 0.f;
#pragma unroll 8
    for (int d = 0; d < 32; d++) acc += rp[d * 32] * W[d * DD + in];
    wdst[row * DD + in] = acc;
    if (in == 0) {
        float bacc = 0.f;
        const float* b = bb2 + t * DD + h * 32;
        for (int d = 0; d < 32; d++) bacc += rp[d * 32] * b[d];
        bdst[row] = bacc;
    }
}

// ---------------- tf32 GEMM (conflict-free scalar-LDS mainloop) ----------------
__global__ void __launch_bounds__(256, 2)
k_gemm2(GemmCfg c0, GemmCfg c1, const float* __restrict__ skipP) {
    GemmCfg c = blockIdx.z ? c1 : c0;
    if (blockIdx.x >= (unsigned)c.gx || blockIdx.y >= (unsigned)c.gy) return;
    __shared__ unsigned sA[128][36];
    __shared__ unsigned sW[128][36];
    int tid = threadIdx.x;
    int lane = tid & 31, wid = tid >> 5;
    int gID = lane >> 2, tig = lane & 3;
    int mw = (wid >> 2) * 64, nw = (wid & 3) * 32;
    int m0 = blockIdx.y * 128, n0 = blockIdx.x * 128;
    int lr = tid >> 1;
    int lc0 = (tid & 1) * 16;
    float acc[4][4][4];
#pragma unroll
    for (int i = 0; i < 4; i++)
#pragma unroll
        for (int j = 0; j < 4; j++)
#pragma unroll
            for (int r = 0; r < 4; r++) acc[i][j][r] = 0.f;

    for (int k0 = 0; k0 < 256; k0 += 32) {
        int gm = m0 + lr;
#pragma unroll
        for (int j = 0; j < 4; j++) {
            int col = k0 + lc0 + j * 4;
            float4 v = make_float4(0.f, 0.f, 0.f, 0.f);
            if (gm < c.M) {
                v = *(const float4*)&c.A[(size_t)gm * c.lda + col];
                if (c.amode == 1) {
                    v.x = gelu1(v.x); v.y = gelu1(v.y);
                    v.z = gelu1(v.z); v.w = gelu1(v.w);
                }
            }
            sA[lr][lc0 + 4 * j + 0] = f2tf32(v.x);
            sA[lr][lc0 + 4 * j + 1] = f2tf32(v.y);
            sA[lr][lc0 + 4 * j + 2] = f2tf32(v.z);
            sA[lr][lc0 + 4 * j + 3] = f2tf32(v.w);
        }
#pragma unroll
        for (int j = 0; j < 4; j++) {
            float4 v = *(const float4*)&c.W[(size_t)(n0 + lr) * 256 + k0 + lc0 + j * 4];
            sW[lr][lc0 + 4 * j + 0] = f2tf32(v.x);
            sW[lr][lc0 + 4 * j + 1] = f2tf32(v.y);
            sW[lr][lc0 + 4 * j + 2] = f2tf32(v.z);
            sW[lr][lc0 + 4 * j + 3] = f2tf32(v.w);
        }
        __syncthreads();
#pragma unroll
        for (int kk = 0; kk < 32; kk += 8) {
            unsigned bfr[4][2];
#pragma unroll
            for (int nt = 0; nt < 4; nt++) {
                int n = nw + nt * 8 + gID;
                bfr[nt][0] = sW[n][kk + tig];
                bfr[nt][1] = sW[n][kk + tig + 4];
            }
#pragma unroll
            for (int mt = 0; mt < 4; mt++) {
                int m = mw + mt * 16 + gID;
                unsigned a0 = sA[m][kk + tig];
                unsigned a1 = sA[m + 8][kk + tig];
                unsigned a2 = sA[m][kk + tig + 4];
                unsigned a3 = sA[m + 8][kk + tig + 4];
#pragma unroll
                for (int nt = 0; nt < 4; nt++)
                    mma_tf32(acc[mt][nt], a0, a1, a2, a3, bfr[nt][0], bfr[nt][1]);
            }
        }
        __syncthreads();
    }

    bool hs = (c.skipX != nullptr);
    float sa = 0.f, sb2 = 0.f;
    if (hs) { float s = skipP[c.skipIdx]; sa = 1.f / (1.f + __expf(-s)); sb2 = 1.f - sa; }
#pragma unroll
    for (int mt = 0; mt < 4; mt++) {
#pragma unroll
        for (int half = 0; half < 2; half++) {
            int m = m0 + mw + mt * 16 + gID + half * 8;
            if (m < c.M) {
#pragma unroll
                for (int nt = 0; nt < 4; nt++) {
                    int n = n0 + nw + nt * 8 + tig * 2;
                    float v0 = acc[mt][nt][half * 2 + 0] + c.bias[n];
                    float v1 = acc[mt][nt][half * 2 + 1] + c.bias[n + 1];
                    if (hs) {
                        v0 = sa * v0 + sb2 * c.skipX[(size_t)m * DD + n];
                        v1 = sa * v1 + sb2 * c.skipX[(size_t)m * DD + n + 1];
                    }
                    if (c.outBF) {
                        __nv_bfloat162* cp = (__nv_bfloat162*)((__nv_bfloat16*)c.C + (size_t)m * c.ldc + n);
                        *cp = __floats2bfloat162_rn(v0, v1);
                    } else {
                        *(float2*)((float*)c.C + (size_t)m * c.ldc + n) = make_float2(v0, v1);
                    }
                }
            }
        }
    }
}

// ---------------- CSR gather aggregation (index-preload + 2-way pipeline) -----------
__global__ void k_aggr(const float* __restrict__ prel) {
    __shared__ float sacc[8 * 256];
    __shared__ float sdn[64];
    int lane = threadIdx.x & 31, w = threadIdx.x >> 5;
    int head = lane >> 2;
    if (blockIdx.x < OPB) {
        int d = blockIdx.x * 8 + w;
        const uint4* qrow = (const uint4*)(g_proj_op + (size_t)d * LD_OP);
        float qf[8]; bf8_to_f(qrow[lane], qf);
        float outv[8] = {0.f, 0.f, 0.f, 0.f, 0.f, 0.f, 0.f, 0.f};
#pragma unroll
        for (int tt = 0; tt < 3; tt++) {
            int type = (tt == 2) ? 3 : tt;
            const __nv_bfloat16 *kp, *vp; int ld;
            if (tt == 0)      { kp = g_proj_op + 256; vp = g_proj_op + 1024; ld = LD_OP; }
            else if (tt == 1) { kp = g_proj_op + 512; vp = g_proj_op + 1280; ld = LD_OP; }
            else              { kp = g_proj_m + 256;  vp = g_proj_m + 512;   ld = LD_M; }
            float pr = prel[type * 8 + head] * SCALE;
            int rb = tt * N_OP + d;
            int s = g_off[rb], n = g_cnt[rb];
            const int* lst = g_elist + type * NE + s;
            float acc[8] = {0.f, 0.f, 0.f, 0.f, 0.f, 0.f, 0.f, 0.f};
            float dn = 0.f;
            for (int base = 0; base < n; base += 32) {
                int cnt = min(32, n - base);
                int myidx = (lane < cnt) ? lst[base + lane] : 0;
                int i = 0;
                for (; i + 1 < cnt; i += 2) {
                    int s0 = __shfl_sync(0xffffffffu, myidx, i);
                    int s1 = __shfl_sync(0xffffffffu, myidx, i + 1);
                    uint4 ku0 = *((const uint4*)(kp + (size_t)s0 * ld) + lane);
                    uint4 vu0 = *((const uint4*)(vp + (size_t)s0 * ld) + lane);
                    uint4 ku1 = *((const uint4*)(kp + (size_t)s1 * ld) + lane);
                    uint4 vu1 = *((const uint4*)(vp + (size_t)s1 * ld) + lane);
                    float kf[8], vf[8];
                    bf8_to_f(ku0, kf); bf8_to_f(vu0, vf);
                    float p = 0.f;
#pragma unroll
                    for (int j = 0; j < 8; j++) p += qf[j] * kf[j];
                    p += __shfl_xor_sync(0xffffffffu, p, 1);
                    p += __shfl_xor_sync(0xffffffffu, p, 2);
                    float ex = __expf(p * pr);
                    dn += ex;
#pragma unroll
                    for (int j = 0; j < 8; j++) acc[j] += vf[j] * ex;
                    bf8_to_f(ku1, kf); bf8_to_f(vu1, vf);
                    p = 0.f;
#pragma unroll
                    for (int j = 0; j < 8; j++) p += qf[j] * kf[j];
                    p += __shfl_xor_sync(0xffffffffu, p, 1);
                    p += __shfl_xor_sync(0xffffffffu, p, 2);
                    ex = __expf(p * pr);
                    dn += ex;
#pragma unroll
                    for (int j = 0; j < 8; j++) acc[j] += vf[j] * ex;
                }
                if (i < cnt) {
                    int s0 = __shfl_sync(0xffffffffu, myidx, i);
                    uint4 ku0 = *((const uint4*)(kp + (size_t)s0 * ld) + lane);
                    uint4 vu0 = *((const uint4*)(vp + (size_t)s0 * ld) + lane);
                    float kf[8], vf[8];
                    bf8_to_f(ku0, kf); bf8_to_f(vu0, vf);
                    float p = 0.f;
#pragma unroll
                    for (int j = 0; j < 8; j++) p += qf[j] * kf[j];
                    p += __shfl_xor_sync(0xffffffffu, p, 1);
                    p += __shfl_xor_sync(0xffffffffu, p, 2);
                    float ex = __expf(p * pr);
                    dn += ex;
#pragma unroll
                    for (int j = 0; j < 8; j++) acc[j] += vf[j] * ex;
                }
            }
            if (dn > 0.f) {
                float inv = 1.f / dn;
#pragma unroll
                for (int j = 0; j < 8; j++) outv[j] += acc[j] * inv;
            }
        }
        float* o = &g_out_op[(size_t)d * DD + lane * 8];
        *(float4*)o = make_float4(outv[0], outv[1], outv[2], outv[3]);
        *(float4*)(o + 4) = make_float4(outv[4], outv[5], outv[6], outv[7]);
    } else {
        int d = blockIdx.x - OPB;
        const uint4* qrow = (const uint4*)(g_proj_m + (size_t)d * LD_M);
        float qf[8]; bf8_to_f(qrow[lane], qf);
        float pr = prel[16 + head] * SCALE;
        int rb = 3 * N_OP + d;
        int s = g_off[rb], n = g_cnt[rb];
        const int* lst = g_elist + 2 * NE + s;
        int per = (n + 7) / 8;
        int i0 = w * per, i1 = min(i0 + per, n);
        float acc[8] = {0.f, 0.f, 0.f, 0.f, 0.f, 0.f, 0.f, 0.f};
        float dn = 0.f;
        for (int base = i0; base < i1; base += 32) {
            int cnt = min(32, i1 - base);
            int myidx = (lane < cnt) ? lst[base + lane] : 0;
            for (int i = 0; i < cnt; i++) {
                int src = __shfl_sync(0xffffffffu, myidx, i);
                uint4 ku = *((const uint4*)(g_proj_op + (size_t)src * LD_OP + 768) + lane);
                uint4 vu = *((const uint4*)(g_proj_op + (size_t)src * LD_OP + 1536) + lane);
                float kf[8], vf[8];
                bf8_to_f(ku, kf); bf8_to_f(vu, vf);
                float p = 0.f;
#pragma unroll
                for (int j = 0; j < 8; j++) p += qf[j] * kf[j];
                p += __shfl_xor_sync(0xffffffffu, p, 1);
                p += __shfl_xor_sync(0xffffffffu, p, 2);
                float ex = __expf(p * pr);
                dn += ex;
#pragma unroll
                for (int j = 0; j < 8; j++) acc[j] += vf[j] * ex;
            }
        }
#pragma unroll
        for (int j = 0; j < 8; j++) sacc[w * 256 + lane * 8 + j] = acc[j];
        if ((lane & 3) == 0) sdn[w * 8 + head] = dn;
        __syncthreads();
        int ch = threadIdx.x, hd = ch >> 5;
        float sv = 0.f, Dv = 0.f;
#pragma unroll
        for (int w2 = 0; w2 < 8; w2++) {
            sv += sacc[w2 * 256 + ch];
            Dv += sdn[w2 * 8 + hd];
        }
        g_out_m[(size_t)d * DD + ch] = (Dv > 0.f) ? sv / Dv : 0.f;
    }
}

// ---------------- launch ----------------
extern "C" void kernel_launch(void* const* d_in, const int* in_sizes, int n_in,
                              void* d_out, int out_size) {
    const float* x_op = (const float*)d_in[0];
    const float* x_m  = (const float*)d_in[1];
    const float* dtp  = (const float*)d_in[2];
    const int* ei_mp  = (const int*)d_in[3];
    const int* ei_pr  = (const int*)d_in[4];
    const int* ei_on  = (const int*)d_in[5];
    const int* ei_ho  = (const int*)d_in[6];
    const float* Wt   = (const float*)d_in[7];
    const float* bt   = (const float*)d_in[8];
    const float* lng  = (const float*)d_in[9];
    const float* lnb  = (const float*)d_in[10];
    const float* Wk   = (const float*)d_in[11];
    const float* bk   = (const float*)d_in[12];
    const float* Wq   = (const float*)d_in[13];
    const float* bq   = (const float*)d_in[14];
    const float* Wv   = (const float*)d_in[15];
    const float* bv   = (const float*)d_in[16];
    const float* Wa   = (const float*)d_in[17];
    const float* ba   = (const float*)d_in[18];
    const float* skip = (const float*)d_in[19];
    const float* a_rel = (const float*)d_in[20];
    const float* m_rel = (const float*)d_in[21];
    const float* p_rel = (const float*)d_in[22];
    float* out = (float*)d_out;

    float *p_x0, *p_wop, *p_bop, *p_wm, *p_bm, *p_oop, *p_om;
    __nv_bfloat16 *p_pop, *p_pm;
    cudaGetSymbolAddress((void**)&p_x0, g_x0);
    cudaGetSymbolAddress((void**)&p_pop, g_proj_op);
    cudaGetSymbolAddress((void**)&p_pm, g_proj_m);
    cudaGetSymbolAddress((void**)&p_wop, g_wop);
    cudaGetSymbolAddress((void**)&p_bop, g_bop);
    cudaGetSymbolAddress((void**)&p_wm, g_wm);
    cudaGetSymbolAddress((void**)&p_bm, g_bm);
    cudaGetSymbolAddress((void**)&p_oop, g_out_op);
    cudaGetSymbolAddress((void**)&p_om, g_out_m);

    int E0 = in_sizes[3] / 2, E1 = in_sizes[4] / 2, E2 = in_sizes[5] / 2, E3 = in_sizes[6] / 2;

    int Emax = E0;
    if (E1 > Emax) Emax = E1;
    if (E2 > Emax) Emax = E2;
    if (E3 > Emax) Emax = E3;
    int bpt = (Emax + 255) / 256;
    int bptT = (E0 + 255) / 256;

    // L1: init/zero + temporal stats
    k_initzero<<<NZB + 35, 256>>>(x_op, Wt, bt);
    // L2: temporal moment scatter + CSR count
    k_temporal_count<<<bptT + 4 * bpt, 256>>>(dtp, ei_mp, ei_pr, ei_on, ei_ho,
                                              E0, E1, E2, E3, bptT, bpt);
    // L3: CSR scan
    k_scan<<<4, 1024>>>();
    // L4: batched temporal finalize + CSR scatter + weight stacking
    k_prep4<<<TFB + 4 * bpt + WSB, 256>>>(Wt, bt, lng, lnb,
                                          ei_mp, ei_pr, ei_on, ei_ho, E0, E1, E2, E3, bpt,
                                          Wk, bk, Wq, bq, Wv, bv, a_rel, m_rel);
    // L5: stacked projections (op + machine, bf16 out)
    {
        GemmCfg cOp = {p_x0, p_wop, p_bop, p_pop, N_OP, DD, LD_OP,
                       LD_OP / 128, (N_OP + 127) / 128, nullptr, 0, 1, 0};
        GemmCfg cM  = {x_m, p_wm, p_bm, p_pm, N_M, DD, LD_M,
                       LD_M / 128, (N_M + 127) / 128, nullptr, 0, 1, 0};
        k_gemm2<<<dim3(LD_OP / 128, (N_OP + 127) / 128, 2), 256>>>(cOp, cM, nullptr);
    }
    // L6: CSR gather aggregation
    k_aggr<<<OPB + N_M, 256>>>(p_rel);
    // L7: final GEMMs (GELU on load, gated skip, fp32 to d_out)
    {
        GemmCfg cOp = {p_oop, Wa, ba, out, N_OP, DD, DD,
                       2, (N_OP + 127) / 128, p_x0, 0, 0, 1};
        GemmCfg cM  = {p_om, Wa + 65536, ba + 256, out + (size_t)N_OP * DD, N_M, DD, DD,
                       2, (N_M + 127) / 128, x_m, 1, 0, 1};
        k_gemm2<<<dim3(2, (N_OP + 127) / 128, 2), 256>>>(cOp, cM, skip);
    }
}